// round 16
// baseline (speedup 1.0000x reference)
#include <cuda_runtime.h>
#include <math.h>

// Scratch (static device globals; allocation-free)
__device__ float g_Ahat[1024 * 176];          // [i][h*44+k] = [Q*scale | w*Qg]
__device__ float g_BhatT[44 * 1024 * 4];      // [k4][j][4]  = [K | Kg] transposed
__device__ float g_cjh[1024 * 4];             // [j][h] -0.5*w*|Kg|^2
__device__ float g_Vcat[1024 * 176];          // [j][ V(128) | Vg(48) ]
__device__ float g_logit[(size_t)1024 * 1024 * 4]; // [i][j][h] logits (16MB)
__device__ float g_attn[(size_t)4 * 1024 * 1024];  // [h][i][j] normalized (16MB)
__device__ float g_osp[4][1024 * 128];        // o_s partials per j-split
__device__ float g_optgp[4][1024 * 48];       // o_pt_g partials per j-split
__device__ float g_opair[1024 * 256];

// ---------------------------------------------------------------------------
// kprep: layernorm + projections + frame transforms. grid=256 (4 rows), blk=256
// ---------------------------------------------------------------------------
__global__ __launch_bounds__(256) void kprep(
    const float* __restrict__ single, const float* __restrict__ T,
    const float* __restrict__ w_C,    const float* __restrict__ ln_g,
    const float* __restrict__ ln_b,
    const float* __restrict__ Wq, const float* __restrict__ Wk,
    const float* __restrict__ Wv, const float* __restrict__ Wqpt,
    const float* __restrict__ Wkpt, const float* __restrict__ Wvpt)
{
    __shared__ float zs[128 * 4];    // [d][r]
    __shared__ float proj[4][528];
    __shared__ float red[2][8];

    const int t  = threadIdx.x;
    const int i0 = blockIdx.x * 4;
    const int lane = t & 31, wid = t >> 5;

    for (int pass = 0; pass < 2; pass++) {
        const int r = pass * 2 + (t >> 7);
        const int d = t & 127;
        float x = single[(i0 + r) * 128 + d];
        float s = x, s2 = x * x;
        #pragma unroll
        for (int o = 16; o; o >>= 1) {
            s  += __shfl_xor_sync(0xffffffffu, s,  o);
            s2 += __shfl_xor_sync(0xffffffffu, s2, o);
        }
        if (lane == 0) { red[0][wid] = s; red[1][wid] = s2; }
        __syncthreads();
        const int base = (t >> 7) * 4;
        float sum  = red[0][base] + red[0][base+1] + red[0][base+2] + red[0][base+3];
        float sum2 = red[1][base] + red[1][base+1] + red[1][base+2] + red[1][base+3];
        float mu  = sum * (1.f / 128.f);
        float var = sum2 * (1.f / 128.f) - mu * mu;
        float inv = rsqrtf(var + 1e-5f);
        zs[d * 4 + r] = (x - mu) * inv * ln_g[d] + ln_b[d];
        __syncthreads();
    }

    for (int o = t; o < 528; o += 256) {
        const float* W; int col, ow;
        if      (o < 128) { W = Wq;   col = o;       ow = 128; }
        else if (o < 256) { W = Wk;   col = o - 128; ow = 128; }
        else if (o < 384) { W = Wv;   col = o - 256; ow = 128; }
        else if (o < 432) { W = Wqpt; col = o - 384; ow = 48;  }
        else if (o < 480) { W = Wkpt; col = o - 432; ow = 48;  }
        else              { W = Wvpt; col = o - 480; ow = 48;  }
        float a0 = 0.f, a1 = 0.f, a2 = 0.f, a3 = 0.f;
        #pragma unroll 8
        for (int d = 0; d < 128; d++) {
            float w = W[d * ow + col];
            float4 z = *(const float4*)&zs[d * 4];
            a0 += z.x * w; a1 += z.y * w; a2 += z.z * w; a3 += z.w * w;
        }
        proj[0][o] = a0; proj[1][o] = a1; proj[2][o] = a2; proj[3][o] = a3;
    }
    __syncthreads();

    const float scale = 0.17677669529663687f;   // 1/sqrt(32)
    for (int u = t; u < 512; u += 256) {
        int r = u >> 7, k = u & 127;
        int i = i0 + r, h = k >> 5, d = k & 31;
        int kk = h * 44 + d;
        g_Ahat[i * 176 + kk] = proj[r][k] * scale;
        g_BhatT[(kk >> 2) * 4096 + i * 4 + (kk & 3)] = proj[r][128 + k];
        g_Vcat[i * 176 + k] = proj[r][256 + k];
    }

    if (t < 16) {
        int r = t >> 2, h = t & 3;
        int i = i0 + r;
        float w = log1pf(__expf(w_C[h]));
        float R[3][3], tv[3];
        #pragma unroll
        for (int x = 0; x < 3; x++) {
            #pragma unroll
            for (int y = 0; y < 3; y++) R[x][y] = T[i * 16 + x * 4 + y];
            tv[x] = T[i * 16 + x * 4 + 3];
        }
        float kk2 = 0.f;
        #pragma unroll
        for (int p = 0; p < 4; p++) {
            float q0 = proj[r][384 + h * 12 + p * 3 + 0];
            float q1 = proj[r][384 + h * 12 + p * 3 + 1];
            float q2 = proj[r][384 + h * 12 + p * 3 + 2];
            float k0 = proj[r][432 + h * 12 + p * 3 + 0];
            float k1 = proj[r][432 + h * 12 + p * 3 + 1];
            float k2 = proj[r][432 + h * 12 + p * 3 + 2];
            float v0 = proj[r][480 + h * 12 + p * 3 + 0];
            float v1 = proj[r][480 + h * 12 + p * 3 + 1];
            float v2 = proj[r][480 + h * 12 + p * 3 + 2];
            #pragma unroll
            for (int x = 0; x < 3; x++) {
                float gq = R[x][0] * q0 + R[x][1] * q1 + R[x][2] * q2 + tv[x];
                float gk = R[x][0] * k0 + R[x][1] * k1 + R[x][2] * k2 + tv[x];
                float gv = R[x][0] * v0 + R[x][1] * v1 + R[x][2] * v2 + tv[x];
                int kki = h * 44 + 32 + p * 3 + x;
                g_Ahat[i * 176 + kki] = w * gq;
                g_BhatT[(kki >> 2) * 4096 + i * 4 + (kki & 3)] = gk;
                g_Vcat[i * 176 + 128 + h * 12 + p * 3 + x] = gv;
                kk2 += gk * gk;
            }
        }
        g_cjh[i * 4 + h] = -0.5f * w * kk2;
    }
}

// ---------------------------------------------------------------------------
// klogit: grid=4096 (4i x 64j), blk=256, dyn smem 73472 B.
// Bias phase (r,j) -> smem hop -> dot phase (h,j) with exclusive Bhat ->
// logits staged to smem -> COALESCED float4 store.
// ---------------------------------------------------------------------------
__global__ __launch_bounds__(256) void klogit(const float* __restrict__ pair,
                                              const float* __restrict__ Wb)
{
    extern __shared__ float sm[];
    float* ps   = sm;              // 4*64*68 = 17408 floats (pair tile, then bias/logits)
    float* Ahat = sm + 17408;      // 704
    float* wbs  = Ahat + 704;      // 256

    const int t  = threadIdx.x;
    const int i0 = (blockIdx.x >> 4) * 4;
    const int j0 = (blockIdx.x & 15) * 64;
    const int j  = t & 63;

    // stage pair tile 4 rows x 64 j x 64 c (coalesced)
    const float4* pr4 = (const float4*)pair;
    #pragma unroll
    for (int q = 0; q < 16; q++) {
        int u = q * 256 + t;
        int r = u >> 10, jj = (u >> 4) & 63, c4 = u & 15;
        float4 v = pr4[(size_t)(i0 + r) * 16384 + (size_t)(j0 + jj) * 16 + c4];
        *(float4*)&ps[(r * 64 + jj) * 68 + c4 * 4] = v;
    }
    for (int u = t; u < 704; u += 256) Ahat[u] = g_Ahat[i0 * 176 + u];
    if (t < 256) wbs[t] = Wb[t];
    __syncthreads();

    // ---- bias phase: thread (r = t>>6, j) computes bias4 over h ----
    {
        const int r = t >> 6;
        float bx = 0.f, by = 0.f, bz = 0.f, bw = 0.f;
        const float* prow = &ps[(r * 64 + j) * 68];
        #pragma unroll
        for (int c4 = 0; c4 < 16; c4++) {
            float4 p  = *(const float4*)&prow[c4 * 4];
            float4 w0 = *(const float4*)&wbs[c4 * 16 + 0];
            float4 w1 = *(const float4*)&wbs[c4 * 16 + 4];
            float4 w2 = *(const float4*)&wbs[c4 * 16 + 8];
            float4 w3 = *(const float4*)&wbs[c4 * 16 + 12];
            bx += p.x * w0.x + p.y * w1.x + p.z * w2.x + p.w * w3.x;
            by += p.x * w0.y + p.y * w1.y + p.z * w2.y + p.w * w3.y;
            bz += p.x * w0.z + p.y * w1.z + p.z * w2.z + p.w * w3.z;
            bw += p.x * w0.w + p.y * w1.w + p.z * w2.w + p.w * w3.w;
        }
        __syncthreads();                       // pair tile now dead
        *(float4*)&ps[t * 4] = make_float4(bx, by, bz, bw);  // bs[(r*64+j)][h]
        __syncthreads();
    }

    // ---- dot phase: thread (h = t>>6, j); 11 exclusive Bhat vectors ----
    {
        const int h  = t >> 6;
        const int kb = h * 11;
        const float4* bhat4 = (const float4*)g_BhatT;
        float accd[4] = {0.f, 0.f, 0.f, 0.f};
        #pragma unroll
        for (int kk = 0; kk < 11; kk++) {
            float4 bv = bhat4[(kb + kk) * 1024 + j0 + j];
            #pragma unroll
            for (int rr = 0; rr < 4; rr++) {
                float4 av = *(const float4*)&Ahat[rr * 176 + (kb + kk) * 4];  // broadcast
                accd[rr] += av.x * bv.x + av.y * bv.y + av.z * bv.z + av.w * bv.w;
            }
        }
        const float cj = g_cjh[(j0 + j) * 4 + h];
        // write logits back to the SAME smem slots this thread read bias from
        #pragma unroll
        for (int rr = 0; rr < 4; rr++) {
            float bias = ps[(rr * 64 + j) * 4 + h];
            ps[(rr * 64 + j) * 4 + h] = accd[rr] + bias + cj;
        }
    }
    __syncthreads();

    // ---- coalesced float4 store: thread t owns (r = t>>6, j) ----
    {
        const int rr = t >> 6;
        ((float4*)g_logit)[(size_t)(i0 + rr) * 1024 + j0 + j] = *(const float4*)&ps[t * 4];
    }
}

// ---------------------------------------------------------------------------
// ksm: softmax over one row i -> normalized g_attn[h][i][j]. grid=1024, blk=256
// ---------------------------------------------------------------------------
__global__ __launch_bounds__(256) void ksm()
{
    __shared__ float redm[8 * 4];
    __shared__ float reds[8 * 4];

    const int t = threadIdx.x, i = blockIdx.x;
    const int lane = t & 31, wid = t >> 5;

    const float4* lg = ((const float4*)g_logit) + (size_t)i * 1024;
    float4 v[4];
    #pragma unroll
    for (int q = 0; q < 4; q++) v[q] = lg[q * 256 + t];

    float4 m = v[0];
    #pragma unroll
    for (int q = 1; q < 4; q++) {
        m.x = fmaxf(m.x, v[q].x); m.y = fmaxf(m.y, v[q].y);
        m.z = fmaxf(m.z, v[q].z); m.w = fmaxf(m.w, v[q].w);
    }
    #pragma unroll
    for (int o = 16; o; o >>= 1) {
        m.x = fmaxf(m.x, __shfl_xor_sync(0xffffffffu, m.x, o));
        m.y = fmaxf(m.y, __shfl_xor_sync(0xffffffffu, m.y, o));
        m.z = fmaxf(m.z, __shfl_xor_sync(0xffffffffu, m.z, o));
        m.w = fmaxf(m.w, __shfl_xor_sync(0xffffffffu, m.w, o));
    }
    if (lane == 0) *(float4*)&redm[wid * 4] = m;
    __syncthreads();
    float4 M = *(const float4*)&redm[0];
    #pragma unroll
    for (int w = 1; w < 8; w++) {
        float4 o = *(const float4*)&redm[w * 4];
        M.x = fmaxf(M.x, o.x); M.y = fmaxf(M.y, o.y);
        M.z = fmaxf(M.z, o.z); M.w = fmaxf(M.w, o.w);
    }

    float4 s = make_float4(0.f, 0.f, 0.f, 0.f);
    #pragma unroll
    for (int q = 0; q < 4; q++) {
        v[q].x = __expf(v[q].x - M.x); v[q].y = __expf(v[q].y - M.y);
        v[q].z = __expf(v[q].z - M.z); v[q].w = __expf(v[q].w - M.w);
        s.x += v[q].x; s.y += v[q].y; s.z += v[q].z; s.w += v[q].w;
    }
    #pragma unroll
    for (int o = 16; o; o >>= 1) {
        s.x += __shfl_xor_sync(0xffffffffu, s.x, o);
        s.y += __shfl_xor_sync(0xffffffffu, s.y, o);
        s.z += __shfl_xor_sync(0xffffffffu, s.z, o);
        s.w += __shfl_xor_sync(0xffffffffu, s.w, o);
    }
    if (lane == 0) *(float4*)&reds[wid * 4] = s;
    __syncthreads();
    float4 Z = make_float4(0.f, 0.f, 0.f, 0.f);
    #pragma unroll
    for (int w = 0; w < 8; w++) {
        float4 o = *(const float4*)&reds[w * 4];
        Z.x += o.x; Z.y += o.y; Z.z += o.z; Z.w += o.w;
    }
    float4 iz = make_float4(1.f / Z.x, 1.f / Z.y, 1.f / Z.z, 1.f / Z.w);

    #pragma unroll
    for (int q = 0; q < 4; q++) {
        int j = q * 256 + t;
        size_t ib = (size_t)i * 1024 + j;
        g_attn[ib]           = v[q].x * iz.x;
        g_attn[1048576 + ib] = v[q].y * iz.y;
        g_attn[2097152 + ib] = v[q].z * iz.z;
        g_attn[3145728 + ib] = v[q].w * iz.w;
    }
}

// ---------------------------------------------------------------------------
// kmix: interleaved merged tail GEMMs. grid=1536, blk=256.
//   b % 3 == 2  -> kattnv branch (512 blocks): o_s/o_pt_g partials
//   else        -> kopair branch (1024 blocks): o_pair = attn @ pair
// ---------------------------------------------------------------------------
__global__ __launch_bounds__(256) void kmix(const float* __restrict__ pair)
{
    __shared__ float ps[4 * 1024];            // kopair: [h][j] probs
    __shared__ float red4[16 * 4 * 16 * 4];   // kopair: [g][h][c4][4]

    const int b = blockIdx.x;
    const int t = threadIdx.x;

    if (b % 3 == 2) {
        // ---------------- kattnv branch (id 0..511) ----------------
        const int id = b / 3;
        const int h  = id & 3;
        const int i0 = ((id >> 2) & 31) * 32;
        const int js = id >> 7;            // 0..3
        const int rp = t >> 4;             // rows 2rp, 2rp+1
        const int ng = t & 15;             // active if < 11

        if (ng < 11) {
            const int col = (ng < 8) ? (h * 32 + ng * 4) : (128 + h * 12 + (ng - 8) * 4);
            const int r0 = i0 + rp * 2;
            const float4* ap0 = (const float4*)(g_attn + (size_t)h * 1048576
                                                + (size_t)r0 * 1024 + js * 256);
            const float4* ap1 = ap0 + 256;
            const float* vb = g_Vcat + (size_t)(js * 256) * 176 + col;

            float4 acc0 = make_float4(0,0,0,0);
            float4 acc1 = make_float4(0,0,0,0);

            #pragma unroll 2
            for (int g = 0; g < 64; g++) {
                float4 a0 = ap0[g];
                float4 a1 = ap1[g];
                float4 v0 = *(const float4*)(vb + (size_t)(g * 4 + 0) * 176);
                float4 v1 = *(const float4*)(vb + (size_t)(g * 4 + 1) * 176);
                float4 v2 = *(const float4*)(vb + (size_t)(g * 4 + 2) * 176);
                float4 v3 = *(const float4*)(vb + (size_t)(g * 4 + 3) * 176);
                acc0.x += a0.x * v0.x + a0.y * v1.x + a0.z * v2.x + a0.w * v3.x;
                acc0.y += a0.x * v0.y + a0.y * v1.y + a0.z * v2.y + a0.w * v3.y;
                acc0.z += a0.x * v0.z + a0.y * v1.z + a0.z * v2.z + a0.w * v3.z;
                acc0.w += a0.x * v0.w + a0.y * v1.w + a0.z * v2.w + a0.w * v3.w;
                acc1.x += a1.x * v0.x + a1.y * v1.x + a1.z * v2.x + a1.w * v3.x;
                acc1.y += a1.x * v0.y + a1.y * v1.y + a1.z * v2.y + a1.w * v3.y;
                acc1.z += a1.x * v0.z + a1.y * v1.z + a1.z * v2.z + a1.w * v3.z;
                acc1.w += a1.x * v0.w + a1.y * v1.w + a1.z * v2.w + a1.w * v3.w;
            }

            if (ng < 8) {
                *(float4*)&g_osp[js][r0 * 128 + h * 32 + ng * 4]       = acc0;
                *(float4*)&g_osp[js][(r0 + 1) * 128 + h * 32 + ng * 4] = acc1;
            } else {
                *(float4*)&g_optgp[js][r0 * 48 + h * 12 + (ng - 8) * 4]       = acc0;
                *(float4*)&g_optgp[js][(r0 + 1) * 48 + h * 12 + (ng - 8) * 4] = acc1;
            }
        }
        return;
    }

    // ---------------- kopair branch (id 0..1023) ----------------
    const int i = (b / 3) * 2 + (b % 3);

    // stage attn row (all 4 heads) via float4
    {
        const float4* at4 = (const float4*)g_attn;
        #pragma unroll
        for (int q = 0; q < 4; q++) {
            int u = q * 256 + t;             // float4 index: h = u>>8, j4 = u&255
            *(float4*)&ps[u * 4] =
                at4[(size_t)(u >> 8) * 262144 + (size_t)i * 256 + (u & 255)];
        }
    }
    __syncthreads();

    const int c4 = t & 15, g = t >> 4;
    const float4* prow4 = (const float4*)(pair + (size_t)i * 65536);
    float4 a0 = make_float4(0,0,0,0), a1 = a0, a2 = a0, a3 = a0;

    #pragma unroll 8
    for (int j = g; j < 1024; j += 16) {
        float4 p = prow4[j * 16 + c4];
        float w0 = ps[j], w1 = ps[1024 + j], w2 = ps[2048 + j], w3 = ps[3072 + j];
        a0.x += p.x * w0; a0.y += p.y * w0; a0.z += p.z * w0; a0.w += p.w * w0;
        a1.x += p.x * w1; a1.y += p.y * w1; a1.z += p.z * w1; a1.w += p.w * w1;
        a2.x += p.x * w2; a2.y += p.y * w2; a2.z += p.z * w2; a2.w += p.w * w2;
        a3.x += p.x * w3; a3.y += p.y * w3; a3.z += p.z * w3; a3.w += p.w * w3;
    }
    *(float4*)&red4[((g * 4 + 0) * 16 + c4) * 4] = a0;
    *(float4*)&red4[((g * 4 + 1) * 16 + c4) * 4] = a1;
    *(float4*)&red4[((g * 4 + 2) * 16 + c4) * 4] = a2;
    *(float4*)&red4[((g * 4 + 3) * 16 + c4) * 4] = a3;
    __syncthreads();

    if (t < 64) {
        const int h2 = t >> 4, c2 = t & 15;
        float4 sum = make_float4(0,0,0,0);
        #pragma unroll
        for (int g2 = 0; g2 < 16; g2++) {
            float4 p = *(const float4*)&red4[((g2 * 4 + h2) * 16 + c2) * 4];
            sum.x += p.x; sum.y += p.y; sum.z += p.z; sum.w += p.w;
        }
        *(float4*)&g_opair[i * 256 + h2 * 64 + c2 * 4] = sum;
    }
}

// ---------------------------------------------------------------------------
// kfinal: sum 4 j-split partials, rotation+norm, concat, out = single + f@Wout.
// grid=256 (4 rows/block), blk=512
// ---------------------------------------------------------------------------
__global__ __launch_bounds__(512) void kfinal(
    const float* __restrict__ single, const float* __restrict__ T,
    const float* __restrict__ Wout,   const float* __restrict__ b_out,
    float* __restrict__ out)
{
    __shared__ float fs[448 * 4];        // [k][r]
    __shared__ float part[4 * 4 * 128];  // [quarter][r][d]

    const int t  = threadIdx.x;
    const int i0 = blockIdx.x * 4;

    {
        int r = t & 3, k = t >> 2;
        int idx = (i0 + r) * 128 + k;
        fs[k * 4 + r] = g_osp[0][idx] + g_osp[1][idx] + g_osp[2][idx] + g_osp[3][idx];
    }
    for (int u = t; u < 1024; u += 512) {
        int r = u & 3, k2 = u >> 2;
        fs[(128 + k2) * 4 + r] = g_opair[(i0 + r) * 256 + k2];
    }
    if (t < 64) {
        int r = t >> 4, hp = t & 15, h = hp >> 2, p = hp & 3;
        int i = i0 + r;
        float Rm[3][3], tv[3];
        #pragma unroll
        for (int y = 0; y < 3; y++) {
            #pragma unroll
            for (int x = 0; x < 3; x++) Rm[y][x] = T[i * 16 + y * 4 + x];
            tv[y] = T[i * 16 + y * 4 + 3];
        }
        int gb = i * 48 + h * 12 + p * 3;
        float g0 = g_optgp[0][gb + 0] + g_optgp[1][gb + 0]
                 + g_optgp[2][gb + 0] + g_optgp[3][gb + 0] - tv[0];
        float g1 = g_optgp[0][gb + 1] + g_optgp[1][gb + 1]
                 + g_optgp[2][gb + 1] + g_optgp[3][gb + 1] - tv[1];
        float g2 = g_optgp[0][gb + 2] + g_optgp[1][gb + 2]
                 + g_optgp[2][gb + 2] + g_optgp[3][gb + 2] - tv[2];
        float nrm = 0.f;
        #pragma unroll
        for (int x = 0; x < 3; x++) {
            float v = Rm[0][x] * g0 + Rm[1][x] * g1 + Rm[2][x] * g2;
            fs[(384 + h * 12 + p * 3 + x) * 4 + r] = v;
            nrm += v * v;
        }
        fs[(432 + h * 4 + p) * 4 + r] = sqrtf(nrm);
    }
    __syncthreads();

    const int d = t & 127, q = t >> 7;
    float a0 = 0.f, a1 = 0.f, a2 = 0.f, a3 = 0.f;
    const int k0 = q * 112;
    #pragma unroll 8
    for (int k = k0; k < k0 + 112; k++) {
        float w = Wout[k * 128 + d];
        float4 f = *(const float4*)&fs[k * 4];
        a0 += f.x * w; a1 += f.y * w; a2 += f.z * w; a3 += f.w * w;
    }
    part[(q * 4 + 0) * 128 + d] = a0;
    part[(q * 4 + 1) * 128 + d] = a1;
    part[(q * 4 + 2) * 128 + d] = a2;
    part[(q * 4 + 3) * 128 + d] = a3;
    __syncthreads();

    {
        const int r = t >> 7, dd = t & 127;
        float s = part[(0 * 4 + r) * 128 + dd] + part[(1 * 4 + r) * 128 + dd]
                + part[(2 * 4 + r) * 128 + dd] + part[(3 * 4 + r) * 128 + dd];
        out[(i0 + r) * 128 + dd] = single[(i0 + r) * 128 + dd] + s + b_out[dd];
    }
}

// ---------------------------------------------------------------------------
extern "C" void kernel_launch(void* const* d_in, const int* in_sizes, int n_in,
                              void* d_out, int out_size)
{
    const float* single = (const float*)d_in[0];
    const float* pair   = (const float*)d_in[1];
    const float* T      = (const float*)d_in[2];
    const float* w_C    = (const float*)d_in[3];
    const float* ln_g   = (const float*)d_in[4];
    const float* ln_b   = (const float*)d_in[5];
    const float* Wq     = (const float*)d_in[6];
    const float* Wk     = (const float*)d_in[7];
    const float* Wv     = (const float*)d_in[8];
    const float* Wqpt   = (const float*)d_in[9];
    const float* Wkpt   = (const float*)d_in[10];
    const float* Wvpt   = (const float*)d_in[11];
    const float* Wb     = (const float*)d_in[12];
    const float* Wout   = (const float*)d_in[13];
    const float* b_out  = (const float*)d_in[14];
    float* out = (float*)d_out;

    const int klogit_smem = (17408 + 704 + 256) * 4;   // 73472 B

    static int smem_set = 0;
    if (!smem_set) {
        cudaFuncSetAttribute(klogit, cudaFuncAttributeMaxDynamicSharedMemorySize,
                             klogit_smem);
        smem_set = 1;
    }

    kprep<<<256, 256>>>(single, T, w_C, ln_g, ln_b, Wq, Wk, Wv, Wqpt, Wkpt, Wvpt);
    klogit<<<4096, 256, klogit_smem>>>(pair, Wb);
    ksm<<<1024, 256>>>();
    kmix<<<1536, 256>>>(pair);
    kfinal<<<256, 512>>>(single, T, Wout, b_out, out);
}

// round 17
// speedup vs baseline: 1.0190x; 1.0190x over previous
#include <cuda_runtime.h>
#include <math.h>

// Scratch (static device globals; allocation-free)
__device__ float g_Ahat[1024 * 176];          // [i][h*44+k] = [Q*scale | w*Qg]
__device__ float g_BhatT[44 * 1024 * 4];      // [k4][j][4]  = [K | Kg] transposed
__device__ float g_cjh[1024 * 4];             // [j][h] -0.5*w*|Kg|^2
__device__ float g_Vcat[1024 * 176];          // [j][ V(128) | Vg(48) ]
__device__ float g_logit[(size_t)1024 * 1024 * 4]; // [i][j][h] logits (16MB)
__device__ float g_attn[(size_t)4 * 1024 * 1024];  // [h][i][j] normalized (16MB)
__device__ float g_osp[4][1024 * 128];        // o_s partials per j-split
__device__ float g_optgp[4][1024 * 48];       // o_pt_g partials per j-split
__device__ float g_opair[1024 * 256];

// ---------------------------------------------------------------------------
// kprep: layernorm + projections + frame transforms. grid=256 (4 rows), blk=256
// ---------------------------------------------------------------------------
__global__ __launch_bounds__(256) void kprep(
    const float* __restrict__ single, const float* __restrict__ T,
    const float* __restrict__ w_C,    const float* __restrict__ ln_g,
    const float* __restrict__ ln_b,
    const float* __restrict__ Wq, const float* __restrict__ Wk,
    const float* __restrict__ Wv, const float* __restrict__ Wqpt,
    const float* __restrict__ Wkpt, const float* __restrict__ Wvpt)
{
    __shared__ float zs[128 * 4];    // [d][r]
    __shared__ float proj[4][528];
    __shared__ float red[2][8];

    const int t  = threadIdx.x;
    const int i0 = blockIdx.x * 4;
    const int lane = t & 31, wid = t >> 5;

    for (int pass = 0; pass < 2; pass++) {
        const int r = pass * 2 + (t >> 7);
        const int d = t & 127;
        float x = single[(i0 + r) * 128 + d];
        float s = x, s2 = x * x;
        #pragma unroll
        for (int o = 16; o; o >>= 1) {
            s  += __shfl_xor_sync(0xffffffffu, s,  o);
            s2 += __shfl_xor_sync(0xffffffffu, s2, o);
        }
        if (lane == 0) { red[0][wid] = s; red[1][wid] = s2; }
        __syncthreads();
        const int base = (t >> 7) * 4;
        float sum  = red[0][base] + red[0][base+1] + red[0][base+2] + red[0][base+3];
        float sum2 = red[1][base] + red[1][base+1] + red[1][base+2] + red[1][base+3];
        float mu  = sum * (1.f / 128.f);
        float var = sum2 * (1.f / 128.f) - mu * mu;
        float inv = rsqrtf(var + 1e-5f);
        zs[d * 4 + r] = (x - mu) * inv * ln_g[d] + ln_b[d];
        __syncthreads();
    }

    for (int o = t; o < 528; o += 256) {
        const float* W; int col, ow;
        if      (o < 128) { W = Wq;   col = o;       ow = 128; }
        else if (o < 256) { W = Wk;   col = o - 128; ow = 128; }
        else if (o < 384) { W = Wv;   col = o - 256; ow = 128; }
        else if (o < 432) { W = Wqpt; col = o - 384; ow = 48;  }
        else if (o < 480) { W = Wkpt; col = o - 432; ow = 48;  }
        else              { W = Wvpt; col = o - 480; ow = 48;  }
        float a0 = 0.f, a1 = 0.f, a2 = 0.f, a3 = 0.f;
        #pragma unroll 8
        for (int d = 0; d < 128; d++) {
            float w = W[d * ow + col];
            float4 z = *(const float4*)&zs[d * 4];
            a0 += z.x * w; a1 += z.y * w; a2 += z.z * w; a3 += z.w * w;
        }
        proj[0][o] = a0; proj[1][o] = a1; proj[2][o] = a2; proj[3][o] = a3;
    }
    __syncthreads();

    const float scale = 0.17677669529663687f;   // 1/sqrt(32)
    for (int u = t; u < 512; u += 256) {
        int r = u >> 7, k = u & 127;
        int i = i0 + r, h = k >> 5, d = k & 31;
        int kk = h * 44 + d;
        g_Ahat[i * 176 + kk] = proj[r][k] * scale;
        g_BhatT[(kk >> 2) * 4096 + i * 4 + (kk & 3)] = proj[r][128 + k];
        g_Vcat[i * 176 + k] = proj[r][256 + k];
    }

    if (t < 16) {
        int r = t >> 2, h = t & 3;
        int i = i0 + r;
        float w = log1pf(__expf(w_C[h]));
        float R[3][3], tv[3];
        #pragma unroll
        for (int x = 0; x < 3; x++) {
            #pragma unroll
            for (int y = 0; y < 3; y++) R[x][y] = T[i * 16 + x * 4 + y];
            tv[x] = T[i * 16 + x * 4 + 3];
        }
        float kk2 = 0.f;
        #pragma unroll
        for (int p = 0; p < 4; p++) {
            float q0 = proj[r][384 + h * 12 + p * 3 + 0];
            float q1 = proj[r][384 + h * 12 + p * 3 + 1];
            float q2 = proj[r][384 + h * 12 + p * 3 + 2];
            float k0 = proj[r][432 + h * 12 + p * 3 + 0];
            float k1 = proj[r][432 + h * 12 + p * 3 + 1];
            float k2 = proj[r][432 + h * 12 + p * 3 + 2];
            float v0 = proj[r][480 + h * 12 + p * 3 + 0];
            float v1 = proj[r][480 + h * 12 + p * 3 + 1];
            float v2 = proj[r][480 + h * 12 + p * 3 + 2];
            #pragma unroll
            for (int x = 0; x < 3; x++) {
                float gq = R[x][0] * q0 + R[x][1] * q1 + R[x][2] * q2 + tv[x];
                float gk = R[x][0] * k0 + R[x][1] * k1 + R[x][2] * k2 + tv[x];
                float gv = R[x][0] * v0 + R[x][1] * v1 + R[x][2] * v2 + tv[x];
                int kki = h * 44 + 32 + p * 3 + x;
                g_Ahat[i * 176 + kki] = w * gq;
                g_BhatT[(kki >> 2) * 4096 + i * 4 + (kki & 3)] = gk;
                g_Vcat[i * 176 + 128 + h * 12 + p * 3 + x] = gv;
                kk2 += gk * gk;
            }
        }
        g_cjh[i * 4 + h] = -0.5f * w * kk2;
    }
}

// ---------------------------------------------------------------------------
// klogit (R15 version): grid=4096 (4i x 64j), blk=256, dyn smem 73472 B.
// Bias phase (r,j) -> smem hop -> dot phase (h,j) with exclusive Bhat ->
// direct scatter store.
// ---------------------------------------------------------------------------
__global__ __launch_bounds__(256) void klogit(const float* __restrict__ pair,
                                              const float* __restrict__ Wb)
{
    extern __shared__ float sm[];
    float* ps   = sm;              // 4*64*68 = 17408 floats (pair tile, then bias)
    float* Ahat = sm + 17408;      // 704
    float* wbs  = Ahat + 704;      // 256

    const int t  = threadIdx.x;
    const int i0 = (blockIdx.x >> 4) * 4;
    const int j0 = (blockIdx.x & 15) * 64;
    const int j  = t & 63;

    // stage pair tile 4 rows x 64 j x 64 c (coalesced)
    const float4* pr4 = (const float4*)pair;
    #pragma unroll
    for (int q = 0; q < 16; q++) {
        int u = q * 256 + t;
        int r = u >> 10, jj = (u >> 4) & 63, c4 = u & 15;
        float4 v = pr4[(size_t)(i0 + r) * 16384 + (size_t)(j0 + jj) * 16 + c4];
        *(float4*)&ps[(r * 64 + jj) * 68 + c4 * 4] = v;
    }
    for (int u = t; u < 704; u += 256) Ahat[u] = g_Ahat[i0 * 176 + u];
    if (t < 256) wbs[t] = Wb[t];
    __syncthreads();

    // ---- bias phase: thread (r = t>>6, j) computes bias4 over h ----
    {
        const int r = t >> 6;
        float bx = 0.f, by = 0.f, bz = 0.f, bw = 0.f;
        const float* prow = &ps[(r * 64 + j) * 68];
        #pragma unroll
        for (int c4 = 0; c4 < 16; c4++) {
            float4 p  = *(const float4*)&prow[c4 * 4];
            float4 w0 = *(const float4*)&wbs[c4 * 16 + 0];
            float4 w1 = *(const float4*)&wbs[c4 * 16 + 4];
            float4 w2 = *(const float4*)&wbs[c4 * 16 + 8];
            float4 w3 = *(const float4*)&wbs[c4 * 16 + 12];
            bx += p.x * w0.x + p.y * w1.x + p.z * w2.x + p.w * w3.x;
            by += p.x * w0.y + p.y * w1.y + p.z * w2.y + p.w * w3.y;
            bz += p.x * w0.z + p.y * w1.z + p.z * w2.z + p.w * w3.z;
            bw += p.x * w0.w + p.y * w1.w + p.z * w2.w + p.w * w3.w;
        }
        __syncthreads();                       // pair tile now dead
        *(float4*)&ps[t * 4] = make_float4(bx, by, bz, bw);  // bs[(r*64+j)][h]
        __syncthreads();
    }

    // ---- dot phase: thread (h = t>>6, j); 11 exclusive Bhat vectors ----
    const int h  = t >> 6;
    const int kb = h * 11;
    const float4* bhat4 = (const float4*)g_BhatT;
    float accd[4] = {0.f, 0.f, 0.f, 0.f};
    #pragma unroll
    for (int kk = 0; kk < 11; kk++) {
        float4 bv = bhat4[(kb + kk) * 1024 + j0 + j];
        #pragma unroll
        for (int rr = 0; rr < 4; rr++) {
            float4 av = *(const float4*)&Ahat[rr * 176 + (kb + kk) * 4];  // broadcast
            accd[rr] += av.x * bv.x + av.y * bv.y + av.z * bv.z + av.w * bv.w;
        }
    }
    const float cj = g_cjh[(j0 + j) * 4 + h];
    #pragma unroll
    for (int rr = 0; rr < 4; rr++) {
        float bias = ps[(rr * 64 + j) * 4 + h];
        g_logit[((size_t)(i0 + rr) * 1024 + j0 + j) * 4 + h] = accd[rr] + bias + cj;
    }
}

// ---------------------------------------------------------------------------
// ksm: softmax over one row i -> normalized g_attn[h][i][j]. grid=1024, blk=256
// ---------------------------------------------------------------------------
__global__ __launch_bounds__(256) void ksm()
{
    __shared__ float redm[8 * 4];
    __shared__ float reds[8 * 4];

    const int t = threadIdx.x, i = blockIdx.x;
    const int lane = t & 31, wid = t >> 5;

    const float4* lg = ((const float4*)g_logit) + (size_t)i * 1024;
    float4 v[4];
    #pragma unroll
    for (int q = 0; q < 4; q++) v[q] = lg[q * 256 + t];

    float4 m = v[0];
    #pragma unroll
    for (int q = 1; q < 4; q++) {
        m.x = fmaxf(m.x, v[q].x); m.y = fmaxf(m.y, v[q].y);
        m.z = fmaxf(m.z, v[q].z); m.w = fmaxf(m.w, v[q].w);
    }
    #pragma unroll
    for (int o = 16; o; o >>= 1) {
        m.x = fmaxf(m.x, __shfl_xor_sync(0xffffffffu, m.x, o));
        m.y = fmaxf(m.y, __shfl_xor_sync(0xffffffffu, m.y, o));
        m.z = fmaxf(m.z, __shfl_xor_sync(0xffffffffu, m.z, o));
        m.w = fmaxf(m.w, __shfl_xor_sync(0xffffffffu, m.w, o));
    }
    if (lane == 0) *(float4*)&redm[wid * 4] = m;
    __syncthreads();
    float4 M = *(const float4*)&redm[0];
    #pragma unroll
    for (int w = 1; w < 8; w++) {
        float4 o = *(const float4*)&redm[w * 4];
        M.x = fmaxf(M.x, o.x); M.y = fmaxf(M.y, o.y);
        M.z = fmaxf(M.z, o.z); M.w = fmaxf(M.w, o.w);
    }

    float4 s = make_float4(0.f, 0.f, 0.f, 0.f);
    #pragma unroll
    for (int q = 0; q < 4; q++) {
        v[q].x = __expf(v[q].x - M.x); v[q].y = __expf(v[q].y - M.y);
        v[q].z = __expf(v[q].z - M.z); v[q].w = __expf(v[q].w - M.w);
        s.x += v[q].x; s.y += v[q].y; s.z += v[q].z; s.w += v[q].w;
    }
    #pragma unroll
    for (int o = 16; o; o >>= 1) {
        s.x += __shfl_xor_sync(0xffffffffu, s.x, o);
        s.y += __shfl_xor_sync(0xffffffffu, s.y, o);
        s.z += __shfl_xor_sync(0xffffffffu, s.z, o);
        s.w += __shfl_xor_sync(0xffffffffu, s.w, o);
    }
    if (lane == 0) *(float4*)&reds[wid * 4] = s;
    __syncthreads();
    float4 Z = make_float4(0.f, 0.f, 0.f, 0.f);
    #pragma unroll
    for (int w = 0; w < 8; w++) {
        float4 o = *(const float4*)&reds[w * 4];
        Z.x += o.x; Z.y += o.y; Z.z += o.z; Z.w += o.w;
    }
    float4 iz = make_float4(1.f / Z.x, 1.f / Z.y, 1.f / Z.z, 1.f / Z.w);

    #pragma unroll
    for (int q = 0; q < 4; q++) {
        int j = q * 256 + t;
        size_t ib = (size_t)i * 1024 + j;
        g_attn[ib]           = v[q].x * iz.x;
        g_attn[1048576 + ib] = v[q].y * iz.y;
        g_attn[2097152 + ib] = v[q].z * iz.z;
        g_attn[3145728 + ib] = v[q].w * iz.w;
    }
}

// ---------------------------------------------------------------------------
// kmix: interleaved merged tail GEMMs. grid=1536, blk=256.
//   b % 3 == 2  -> kattnv branch (512 blocks): o_s/o_pt_g partials
//   else        -> kopair branch (1024 blocks): o_pair = attn @ pair
// ---------------------------------------------------------------------------
__global__ __launch_bounds__(256) void kmix(const float* __restrict__ pair)
{
    __shared__ float ps[4 * 1024];            // kopair: [h][j] probs
    __shared__ float red4[16 * 4 * 16 * 4];   // kopair: [g][h][c4][4]

    const int b = blockIdx.x;
    const int t = threadIdx.x;

    if (b % 3 == 2) {
        // ---------------- kattnv branch (id 0..511) ----------------
        const int id = b / 3;
        const int h  = id & 3;
        const int i0 = ((id >> 2) & 31) * 32;
        const int js = id >> 7;            // 0..3
        const int rp = t >> 4;             // rows 2rp, 2rp+1
        const int ng = t & 15;             // active if < 11

        if (ng < 11) {
            const int col = (ng < 8) ? (h * 32 + ng * 4) : (128 + h * 12 + (ng - 8) * 4);
            const int r0 = i0 + rp * 2;
            const float4* ap0 = (const float4*)(g_attn + (size_t)h * 1048576
                                                + (size_t)r0 * 1024 + js * 256);
            const float4* ap1 = ap0 + 256;
            const float* vb = g_Vcat + (size_t)(js * 256) * 176 + col;

            float4 acc0 = make_float4(0,0,0,0);
            float4 acc1 = make_float4(0,0,0,0);

            #pragma unroll 2
            for (int g = 0; g < 64; g++) {
                float4 a0 = ap0[g];
                float4 a1 = ap1[g];
                float4 v0 = *(const float4*)(vb + (size_t)(g * 4 + 0) * 176);
                float4 v1 = *(const float4*)(vb + (size_t)(g * 4 + 1) * 176);
                float4 v2 = *(const float4*)(vb + (size_t)(g * 4 + 2) * 176);
                float4 v3 = *(const float4*)(vb + (size_t)(g * 4 + 3) * 176);
                acc0.x += a0.x * v0.x + a0.y * v1.x + a0.z * v2.x + a0.w * v3.x;
                acc0.y += a0.x * v0.y + a0.y * v1.y + a0.z * v2.y + a0.w * v3.y;
                acc0.z += a0.x * v0.z + a0.y * v1.z + a0.z * v2.z + a0.w * v3.z;
                acc0.w += a0.x * v0.w + a0.y * v1.w + a0.z * v2.w + a0.w * v3.w;
                acc1.x += a1.x * v0.x + a1.y * v1.x + a1.z * v2.x + a1.w * v3.x;
                acc1.y += a1.x * v0.y + a1.y * v1.y + a1.z * v2.y + a1.w * v3.y;
                acc1.z += a1.x * v0.z + a1.y * v1.z + a1.z * v2.z + a1.w * v3.z;
                acc1.w += a1.x * v0.w + a1.y * v1.w + a1.z * v2.w + a1.w * v3.w;
            }

            if (ng < 8) {
                *(float4*)&g_osp[js][r0 * 128 + h * 32 + ng * 4]       = acc0;
                *(float4*)&g_osp[js][(r0 + 1) * 128 + h * 32 + ng * 4] = acc1;
            } else {
                *(float4*)&g_optgp[js][r0 * 48 + h * 12 + (ng - 8) * 4]       = acc0;
                *(float4*)&g_optgp[js][(r0 + 1) * 48 + h * 12 + (ng - 8) * 4] = acc1;
            }
        }
        return;
    }

    // ---------------- kopair branch (id 0..1023) ----------------
    const int i = (b / 3) * 2 + (b % 3);

    // stage attn row (all 4 heads) via float4
    {
        const float4* at4 = (const float4*)g_attn;
        #pragma unroll
        for (int q = 0; q < 4; q++) {
            int u = q * 256 + t;             // float4 index: h = u>>8, j4 = u&255
            *(float4*)&ps[u * 4] =
                at4[(size_t)(u >> 8) * 262144 + (size_t)i * 256 + (u & 255)];
        }
    }
    __syncthreads();

    const int c4 = t & 15, g = t >> 4;
    const float4* prow4 = (const float4*)(pair + (size_t)i * 65536);
    float4 a0 = make_float4(0,0,0,0), a1 = a0, a2 = a0, a3 = a0;

    #pragma unroll 8
    for (int j = g; j < 1024; j += 16) {
        float4 p = prow4[j * 16 + c4];
        float w0 = ps[j], w1 = ps[1024 + j], w2 = ps[2048 + j], w3 = ps[3072 + j];
        a0.x += p.x * w0; a0.y += p.y * w0; a0.z += p.z * w0; a0.w += p.w * w0;
        a1.x += p.x * w1; a1.y += p.y * w1; a1.z += p.z * w1; a1.w += p.w * w1;
        a2.x += p.x * w2; a2.y += p.y * w2; a2.z += p.z * w2; a2.w += p.w * w2;
        a3.x += p.x * w3; a3.y += p.y * w3; a3.z += p.z * w3; a3.w += p.w * w3;
    }
    *(float4*)&red4[((g * 4 + 0) * 16 + c4) * 4] = a0;
    *(float4*)&red4[((g * 4 + 1) * 16 + c4) * 4] = a1;
    *(float4*)&red4[((g * 4 + 2) * 16 + c4) * 4] = a2;
    *(float4*)&red4[((g * 4 + 3) * 16 + c4) * 4] = a3;
    __syncthreads();

    if (t < 64) {
        const int h2 = t >> 4, c2 = t & 15;
        float4 sum = make_float4(0,0,0,0);
        #pragma unroll
        for (int g2 = 0; g2 < 16; g2++) {
            float4 p = *(const float4*)&red4[((g2 * 4 + h2) * 16 + c2) * 4];
            sum.x += p.x; sum.y += p.y; sum.z += p.z; sum.w += p.w;
        }
        *(float4*)&g_opair[i * 256 + h2 * 64 + c2 * 4] = sum;
    }
}

// ---------------------------------------------------------------------------
// kfinal: sum 4 j-split partials, rotation+norm, concat, out = single + f@Wout.
// grid=256 (4 rows/block), blk=512
// ---------------------------------------------------------------------------
__global__ __launch_bounds__(512) void kfinal(
    const float* __restrict__ single, const float* __restrict__ T,
    const float* __restrict__ Wout,   const float* __restrict__ b_out,
    float* __restrict__ out)
{
    __shared__ float fs[448 * 4];        // [k][r]
    __shared__ float part[4 * 4 * 128];  // [quarter][r][d]

    const int t  = threadIdx.x;
    const int i0 = blockIdx.x * 4;

    {
        int r = t & 3, k = t >> 2;
        int idx = (i0 + r) * 128 + k;
        fs[k * 4 + r] = g_osp[0][idx] + g_osp[1][idx] + g_osp[2][idx] + g_osp[3][idx];
    }
    for (int u = t; u < 1024; u += 512) {
        int r = u & 3, k2 = u >> 2;
        fs[(128 + k2) * 4 + r] = g_opair[(i0 + r) * 256 + k2];
    }
    if (t < 64) {
        int r = t >> 4, hp = t & 15, h = hp >> 2, p = hp & 3;
        int i = i0 + r;
        float Rm[3][3], tv[3];
        #pragma unroll
        for (int y = 0; y < 3; y++) {
            #pragma unroll
            for (int x = 0; x < 3; x++) Rm[y][x] = T[i * 16 + y * 4 + x];
            tv[y] = T[i * 16 + y * 4 + 3];
        }
        int gb = i * 48 + h * 12 + p * 3;
        float g0 = g_optgp[0][gb + 0] + g_optgp[1][gb + 0]
                 + g_optgp[2][gb + 0] + g_optgp[3][gb + 0] - tv[0];
        float g1 = g_optgp[0][gb + 1] + g_optgp[1][gb + 1]
                 + g_optgp[2][gb + 1] + g_optgp[3][gb + 1] - tv[1];
        float g2 = g_optgp[0][gb + 2] + g_optgp[1][gb + 2]
                 + g_optgp[2][gb + 2] + g_optgp[3][gb + 2] - tv[2];
        float nrm = 0.f;
        #pragma unroll
        for (int x = 0; x < 3; x++) {
            float v = Rm[0][x] * g0 + Rm[1][x] * g1 + Rm[2][x] * g2;
            fs[(384 + h * 12 + p * 3 + x) * 4 + r] = v;
            nrm += v * v;
        }
        fs[(432 + h * 4 + p) * 4 + r] = sqrtf(nrm);
    }
    __syncthreads();

    const int d = t & 127, q = t >> 7;
    float a0 = 0.f, a1 = 0.f, a2 = 0.f, a3 = 0.f;
    const int k0 = q * 112;
    #pragma unroll 8
    for (int k = k0; k < k0 + 112; k++) {
        float w = Wout[k * 128 + d];
        float4 f = *(const float4*)&fs[k * 4];
        a0 += f.x * w; a1 += f.y * w; a2 += f.z * w; a3 += f.w * w;
    }
    part[(q * 4 + 0) * 128 + d] = a0;
    part[(q * 4 + 1) * 128 + d] = a1;
    part[(q * 4 + 2) * 128 + d] = a2;
    part[(q * 4 + 3) * 128 + d] = a3;
    __syncthreads();

    {
        const int r = t >> 7, dd = t & 127;
        float s = part[(0 * 4 + r) * 128 + dd] + part[(1 * 4 + r) * 128 + dd]
                + part[(2 * 4 + r) * 128 + dd] + part[(3 * 4 + r) * 128 + dd];
        out[(i0 + r) * 128 + dd] = single[(i0 + r) * 128 + dd] + s + b_out[dd];
    }
}

// ---------------------------------------------------------------------------
extern "C" void kernel_launch(void* const* d_in, const int* in_sizes, int n_in,
                              void* d_out, int out_size)
{
    const float* single = (const float*)d_in[0];
    const float* pair   = (const float*)d_in[1];
    const float* T      = (const float*)d_in[2];
    const float* w_C    = (const float*)d_in[3];
    const float* ln_g   = (const float*)d_in[4];
    const float* ln_b   = (const float*)d_in[5];
    const float* Wq     = (const float*)d_in[6];
    const float* Wk     = (const float*)d_in[7];
    const float* Wv     = (const float*)d_in[8];
    const float* Wqpt   = (const float*)d_in[9];
    const float* Wkpt   = (const float*)d_in[10];
    const float* Wvpt   = (const float*)d_in[11];
    const float* Wb     = (const float*)d_in[12];
    const float* Wout   = (const float*)d_in[13];
    const float* b_out  = (const float*)d_in[14];
    float* out = (float*)d_out;

    const int klogit_smem = (17408 + 704 + 256) * 4;   // 73472 B

    static int smem_set = 0;
    if (!smem_set) {
        cudaFuncSetAttribute(klogit, cudaFuncAttributeMaxDynamicSharedMemorySize,
                             klogit_smem);
        smem_set = 1;
    }

    kprep<<<256, 256>>>(single, T, w_C, ln_g, ln_b, Wq, Wk, Wv, Wqpt, Wkpt, Wvpt);
    klogit<<<4096, 256, klogit_smem>>>(pair, Wb);
    ksm<<<1024, 256>>>();
    kmix<<<1536, 256>>>(pair);
    kfinal<<<256, 512>>>(single, T, Wout, b_out, out);
}